// round 11
// baseline (speedup 1.0000x reference)
#include <cuda_runtime.h>
#include <math.h>

// D_MODEL=300, L=512, B=512, OUT=4.
// diag[e,i] = fmap[i,i,e] = sum_l e2[i,l,i] * e1[i,l,e], i in [0,300)
// Split:  diag[e,i] = scale * sum_l s[i,l]*emb1[x1[i,l]][e]      (term1, gather)
//                   +          sum_l s[i,l]*pe[l][e]             (term2, dense GEMM)
// with    s[i,l] = emb2[x2[i,l]][i]*scale + pe[l][i]
// All partial sums now accumulate via atomicAdd into one zeroed buffer.

#define D     300
#define LSEQ  512
#define OUTC  4
#define NCH   4     // term1 l-split
#define CHUNK 128   // LSEQ / NCH
#define DKZ   4     // combine K-split (128 per block)
#define HKZ   5     // fc1 K-split
#define KT1   60    // fc1 K per block (5*60=300)

__device__ float g_pe[LSEQ * D];          // [l][d]
__device__ float g_s[D * LSEQ];           // [i][l]
__device__ float g_acc[2 * D * D];        // [0:D*D) diag [e][i]; [D*D:) hidden [e][j]

#define G_DIAG (g_acc)
#define G_HACC (g_acc + D * D)

// ---- packed f32x2 helpers (sm_103a) ----------------------------------------
__device__ __forceinline__ unsigned long long pack2(float x, float y) {
    unsigned long long r;
    asm("mov.b64 %0, {%1, %2};" : "=l"(r) : "f"(x), "f"(y));
    return r;
}
__device__ __forceinline__ unsigned long long fma2(unsigned long long a,
                                                   unsigned long long b,
                                                   unsigned long long c) {
    unsigned long long d;
    asm("fma.rn.f32x2 %0, %1, %2, %3;" : "=l"(d) : "l"(a), "l"(b), "l"(c));
    return d;
}
__device__ __forceinline__ float2 unpack2(unsigned long long v) {
    float2 r;
    asm("mov.b64 {%0, %1}, %2;" : "=f"(r.x), "=f"(r.y) : "l"(v));
    return r;
}

// ---------------------------------------------------------------------------
// Kernel 0: zero the accumulator + positional encoding (float32, matches jnp).
// ---------------------------------------------------------------------------
__global__ void pe_kernel() {
    const int gid  = blockIdx.x * blockDim.x + threadIdx.x;
    const int nthr = gridDim.x * blockDim.x;
    for (int z = gid; z < 2 * D * D; z += nthr) g_acc[z] = 0.f;

    if (gid < LSEQ * D) {
        int l = gid / D;
        int d = gid % D;
        int k = d >> 1;
        const float coef = -9.210340371976184f / (float)D;   // -ln(10000)/300
        float divv = expf((float)(2 * k) * coef);
        float ang  = (float)l * divv;
        g_pe[gid] = (d & 1) ? cosf(ang) : sinf(ang);
    }
}

// ---------------------------------------------------------------------------
// Kernel 1: term1. One block per (i, l-chunk of 128). grid (4,300).
// Epilogue atomically adds scale * partial into G_DIAG.
// ---------------------------------------------------------------------------
__global__ __launch_bounds__(320) void term1_kernel(
    const int*   __restrict__ x1,
    const int*   __restrict__ x2,
    const float* __restrict__ emb1,
    const float* __restrict__ emb2)
{
    const int chunk = blockIdx.x;          // 0..3
    const int i     = blockIdx.y;          // 0..299
    const int tid   = threadIdx.x;
    const float scale = 17.320508075688775f;  // sqrt(300)

    __shared__ float s_sh[CHUNK];
    __shared__ int   r1_sh[CHUNK];

    if (tid < CHUNK) {
        int l  = chunk * CHUNK + tid;
        int t2 = x2[i * LSEQ + l];
        float sv = fmaf(emb2[t2 * D + i], scale, g_pe[l * D + i]);
        s_sh[tid] = sv;
        g_s[i * LSEQ + l] = sv;
        r1_sh[tid] = x1[i * LSEQ + l] * D;
    }
    __syncthreads();

    if (tid < D) {
        const int e = tid;
        float acc[8];
        #pragma unroll
        for (int u = 0; u < 8; ++u) acc[u] = 0.f;
        #pragma unroll 2
        for (int l = 0; l < CHUNK; l += 8) {
            #pragma unroll
            for (int u = 0; u < 8; ++u)
                acc[u] = fmaf(s_sh[l + u], emb1[r1_sh[l + u] + e], acc[u]);
        }
        float r = ((acc[0] + acc[1]) + (acc[2] + acc[3]))
                + ((acc[4] + acc[5]) + (acc[6] + acc[7]));
        atomicAdd(&G_DIAG[e * D + i], scale * r);
    }
}

// ---------------------------------------------------------------------------
// Kernel 2: term2 GEMM, atomically accumulated into G_DIAG.
//   G_DIAG[e][i] += sum_{l in 128-window kz} s[i,l]*pe[l][e]
// grid (10,10,4), 128 threads (16,8). Thread tile 4e x 2i.
// Inner loop: LDS.64(s) + LDS.128(pe) + 2 packs + 4 FFMA2.
// ---------------------------------------------------------------------------
__global__ __launch_bounds__(128) void combine_kernel()
{
    __shared__ float sh_st[128][34];   // [k][i_local]
    __shared__ float sh_pe[128][36];   // [k][e_local], 16B-aligned rows

    const int tx  = threadIdx.x;       // 0..15 -> i = i0 + 2*tx + {0,1}
    const int ty  = threadIdx.y;       // 0..7  -> e = e0 + 4*ty + {0..3}
    const int lin = ty * 16 + tx;
    const int e0  = blockIdx.x * 32;
    const int i0  = blockIdx.y * 32;
    const int kb  = blockIdx.z * 128;

    // stage s tile transposed: 32 i-rows x 128 k
    #pragma unroll
    for (int t = 0; t < 8; ++t) {
        int idx = lin + t * 128;           // 0..1023
        int row = idx >> 5;                // 0..31 (i_local)
        int kk  = (idx & 31) * 4;          // 0..124
        float4 v = make_float4(0.f, 0.f, 0.f, 0.f);
        int ii = i0 + row;
        if (ii < D)
            v = *reinterpret_cast<const float4*>(g_s + ii * LSEQ + kb + kk);
        sh_st[kk][row] = v.x; sh_st[kk + 1][row] = v.y;
        sh_st[kk + 2][row] = v.z; sh_st[kk + 3][row] = v.w;
    }
    // stage pe tile (naturally k-major): 128 k-rows x 32 e
    #pragma unroll
    for (int t = 0; t < 8; ++t) {
        int idx = lin + t * 128;           // 0..1023
        int row = idx >> 3;                // 0..127 (k_local)
        int cc  = (idx & 7) * 4;           // 0..28
        int e   = e0 + cc;
        float4 v = make_float4(0.f, 0.f, 0.f, 0.f);
        if (e <= D - 4)
            v = *reinterpret_cast<const float4*>(g_pe + (kb + row) * D + e);
        *reinterpret_cast<float4*>(&sh_pe[row][cc]) = v;
    }
    __syncthreads();

    unsigned long long A0 = 0, A1 = 0, B0 = 0, B1 = 0;
    #pragma unroll 4
    for (int k = 0; k < 128; ++k) {
        float2 sv = *reinterpret_cast<const float2*>(&sh_st[k][2 * tx]);
        ulonglong2 pv = *reinterpret_cast<const ulonglong2*>(&sh_pe[k][4 * ty]);
        unsigned long long bxx = pack2(sv.x, sv.x);
        unsigned long long byy = pack2(sv.y, sv.y);
        A0 = fma2(bxx, pv.x, A0);   // i=ip,   e=(4ty, 4ty+1)
        A1 = fma2(bxx, pv.y, A1);   // i=ip,   e=(4ty+2, 4ty+3)
        B0 = fma2(byy, pv.x, B0);   // i=ip+1
        B1 = fma2(byy, pv.y, B1);
    }

    const int ip = i0 + 2 * tx;            // even pair (ip, ip+1)
    const int e  = e0 + 4 * ty;
    if (ip < D) {
        float2 a0 = unpack2(A0), a1 = unpack2(A1);
        float2 b0 = unpack2(B0), b1 = unpack2(B1);
        if (e + 0 < D) { atomicAdd(&G_DIAG[(e + 0) * D + ip], a0.x);
                         atomicAdd(&G_DIAG[(e + 0) * D + ip + 1], b0.x); }
        if (e + 1 < D) { atomicAdd(&G_DIAG[(e + 1) * D + ip], a0.y);
                         atomicAdd(&G_DIAG[(e + 1) * D + ip + 1], b0.y); }
        if (e + 2 < D) { atomicAdd(&G_DIAG[(e + 2) * D + ip], a1.x);
                         atomicAdd(&G_DIAG[(e + 2) * D + ip + 1], b1.x); }
        if (e + 3 < D) { atomicAdd(&G_DIAG[(e + 3) * D + ip], a1.y);
                         atomicAdd(&G_DIAG[(e + 3) * D + ip + 1], b1.y); }
    }
}

// ---------------------------------------------------------------------------
// Kernel 3: FC1, atomically accumulated into G_HACC.
//   G_HACC[e][j] += sum_{k in 60-window} diag[e][k] * w1[j][k]
// Single-plane diag staging. w1 tile stored LANE-DUPLICATED so the inner
// loop is 2 x LDS.128 + 4 FFMA2 (6 issue slots / 16 FLOP).
// ---------------------------------------------------------------------------
__global__ __launch_bounds__(128) void fc1_kernel(
    const float* __restrict__ w1)
{
    __shared__ float sat[KT1][36];      // [k][e_local]           (144B rows)
    __shared__ float sbt[KT1][68];      // [k][dup j_local pairs] (272B rows)

    const int tx  = threadIdx.x;        // 0..15 -> j = j0 + 2*tx + {0,1}
    const int ty  = threadIdx.y;        // 0..7  -> e = e0 + 4*ty + {0..3}
    const int lin = ty * 16 + tx;
    const int j0  = blockIdx.x * 32;
    const int e0  = blockIdx.y * 32;
    const int kb  = blockIdx.z * KT1;

    // stage: 32 rows x 15 float4 per operand, written transposed;
    // w1 written duplicated: sbt[k][2*jl], sbt[k][2*jl+1] both = w1[j][k].
    for (int idx = lin; idx < 32 * 15; idx += 128) {
        int row = idx / 15;                 // e_local / j_local
        int kk  = (idx % 15) * 4;
        int k   = kb + kk;                  // max 240+56+3 = 299 < 300
        float4 va = make_float4(0.f, 0.f, 0.f, 0.f);
        float4 vb = va;
        if (e0 + row < D)
            va = *reinterpret_cast<const float4*>(G_DIAG + (e0 + row) * D + k);
        if (j0 + row < D)
            vb = *reinterpret_cast<const float4*>(w1 + (j0 + row) * D + k);
        sat[kk][row] = va.x; sat[kk + 1][row] = va.y;
        sat[kk + 2][row] = va.z; sat[kk + 3][row] = va.w;
        *reinterpret_cast<float2*>(&sbt[kk][2 * row])     = make_float2(vb.x, vb.x);
        *reinterpret_cast<float2*>(&sbt[kk + 1][2 * row]) = make_float2(vb.y, vb.y);
        *reinterpret_cast<float2*>(&sbt[kk + 2][2 * row]) = make_float2(vb.z, vb.z);
        *reinterpret_cast<float2*>(&sbt[kk + 3][2 * row]) = make_float2(vb.w, vb.w);
    }
    __syncthreads();

    unsigned long long A0 = 0, A1 = 0, B0 = 0, B1 = 0;
    #pragma unroll 6
    for (int k = 0; k < KT1; ++k) {
        ulonglong2 av = *reinterpret_cast<const ulonglong2*>(&sat[k][4 * ty]);
        ulonglong2 bv = *reinterpret_cast<const ulonglong2*>(&sbt[k][4 * tx]);
        A0 = fma2(bv.x, av.x, A0);   // j=jp,   e=(4ty, 4ty+1)
        A1 = fma2(bv.x, av.y, A1);   // j=jp,   e=(4ty+2, 4ty+3)
        B0 = fma2(bv.y, av.x, B0);   // j=jp+1
        B1 = fma2(bv.y, av.y, B1);
    }

    const int jp = j0 + 2 * tx;             // even pair
    const int e  = e0 + 4 * ty;
    if (jp < D) {
        float2 a0 = unpack2(A0), a1 = unpack2(A1);
        float2 b0 = unpack2(B0), b1 = unpack2(B1);
        if (e + 0 < D) { atomicAdd(&G_HACC[(e + 0) * D + jp], a0.x);
                         atomicAdd(&G_HACC[(e + 0) * D + jp + 1], b0.x); }
        if (e + 1 < D) { atomicAdd(&G_HACC[(e + 1) * D + jp], a0.y);
                         atomicAdd(&G_HACC[(e + 1) * D + jp + 1], b0.y); }
        if (e + 2 < D) { atomicAdd(&G_HACC[(e + 2) * D + jp], a1.x);
                         atomicAdd(&G_HACC[(e + 2) * D + jp + 1], b1.x); }
        if (e + 3 < D) { atomicAdd(&G_HACC[(e + 3) * D + jp], a1.y);
                         atomicAdd(&G_HACC[(e + 3) * D + jp + 1], b1.y); }
    }
}

// ---------------------------------------------------------------------------
// Kernel 4: FC2 + softmax. One block per e-row. Bias + ReLU + dot + softmax.
// ---------------------------------------------------------------------------
__global__ __launch_bounds__(128) void fc2_kernel(
    const float* __restrict__ b1,
    const float* __restrict__ w2,
    const float* __restrict__ b2,
    float*       __restrict__ out)
{
    const int e   = blockIdx.x;
    const int tid = threadIdx.x;

    float p[OUTC] = {0.f, 0.f, 0.f, 0.f};
    for (int j = tid; j < D; j += 128) {
        float hv = fmaxf(G_HACC[e * D + j] + b1[j], 0.f);
        #pragma unroll
        for (int o = 0; o < OUTC; ++o)
            p[o] = fmaf(hv, w2[o * D + j], p[o]);
    }

    #pragma unroll
    for (int off = 16; off > 0; off >>= 1) {
        #pragma unroll
        for (int o = 0; o < OUTC; ++o)
            p[o] += __shfl_xor_sync(0xFFFFFFFFu, p[o], off);
    }

    __shared__ float red[4][OUTC];
    const int wid = tid >> 5, lid = tid & 31;
    if (lid == 0) {
        #pragma unroll
        for (int o = 0; o < OUTC; ++o) red[wid][o] = p[o];
    }
    __syncthreads();

    if (tid == 0) {
        float logits[OUTC];
        #pragma unroll
        for (int o = 0; o < OUTC; ++o)
            logits[o] = red[0][o] + red[1][o] + red[2][o] + red[3][o] + b2[o];
        float m = fmaxf(fmaxf(logits[0], logits[1]), fmaxf(logits[2], logits[3]));
        float es[OUTC], ssum = 0.f;
        #pragma unroll
        for (int o = 0; o < OUTC; ++o) { es[o] = expf(logits[o] - m); ssum += es[o]; }
        float inv = 1.f / ssum;
        #pragma unroll
        for (int o = 0; o < OUTC; ++o) out[e * OUTC + o] = es[o] * inv;
    }
}

// ---------------------------------------------------------------------------
// Launch. Inputs: x1, x2 (i32 [512*512]); emb1, emb2 (f32 [32000*300]);
// w1 (f32 [300*300]); b1 (f32 [300]); w2 (f32 [4*300]); b2 (f32 [4]).
// Output: f32 [300*4].
// ---------------------------------------------------------------------------
extern "C" void kernel_launch(void* const* d_in, const int* in_sizes, int n_in,
                              void* d_out, int out_size) {
    const int*   x1   = (const int*)  d_in[0];
    const int*   x2   = (const int*)  d_in[1];
    const float* emb1 = (const float*)d_in[2];
    const float* emb2 = (const float*)d_in[3];
    const float* w1   = (const float*)d_in[4];
    const float* b1   = (const float*)d_in[5];
    const float* w2   = (const float*)d_in[6];
    const float* b2   = (const float*)d_in[7];
    float* out = (float*)d_out;

    pe_kernel<<<(LSEQ * D + 255) / 256, 256>>>();
    dim3 g1(NCH, D);
    term1_kernel<<<g1, 320>>>(x1, x2, emb1, emb2);
    combine_kernel<<<dim3(10, 10, DKZ), dim3(16, 8)>>>();
    fc1_kernel<<<dim3(10, 10, HKZ), dim3(16, 8)>>>(w1);
    fc2_kernel<<<D, 128>>>(b1, w2, b2, out);
}

// round 12
// speedup vs baseline: 1.0172x; 1.0172x over previous
#include <cuda_runtime.h>
#include <math.h>

// D_MODEL=300, L=512, B=512, OUT=4.
// diag[e,i] = fmap[i,i,e] = sum_l e2[i,l,i] * e1[i,l,e], i in [0,300)
// Split:  diag[e,i] = scale * sum_l s[i,l]*emb1[x1[i,l]][e]      (term1, gather)
//                   +          sum_l s[i,l]*pe[l][e]             (term2, dense GEMM)
// with    s[i,l] = emb2[x2[i,l]][i]*scale + pe[l][i]
// Accumulation into one zeroed buffer via atomicAdd; pipeline overlapped with
// programmatic dependent launch (PDL / griddepcontrol).

#define D     300
#define LSEQ  512
#define OUTC  4
#define NCH   4     // term1 l-split
#define CHUNK 128   // LSEQ / NCH
#define DKZ   4     // combine K-split (128 per block)
#define HKZ   5     // fc1 K-split
#define KT1   60    // fc1 K per block (5*60=300)

__device__ float g_pe[LSEQ * D];          // [l][d]
__device__ float g_s[D * LSEQ];           // [i][l]
__device__ float g_acc[2 * D * D];        // [0:D*D) diag [e][i]; [D*D:) hidden [e][j]

#define G_DIAG (g_acc)
#define G_HACC (g_acc + D * D)

#define GDC_LAUNCH() asm volatile("griddepcontrol.launch_dependents;")
#define GDC_WAIT()   asm volatile("griddepcontrol.wait;" ::: "memory")

// ---------------------------------------------------------------------------
// Kernel A: zero the accumulator. Tiny; runs first.
// ---------------------------------------------------------------------------
__global__ void zero_kernel() {
    int idx = blockIdx.x * blockDim.x + threadIdx.x;   // float4 index
    if (idx < (2 * D * D) / 4)
        reinterpret_cast<float4*>(g_acc)[idx] = make_float4(0.f, 0.f, 0.f, 0.f);
}

// ---------------------------------------------------------------------------
// Kernel B: positional encoding (float32, matches jnp float32 path).
// Fires launch_dependents at entry so term1 runs fully concurrent.
// ---------------------------------------------------------------------------
__global__ void pe_kernel() {
    GDC_LAUNCH();
    int idx = blockIdx.x * blockDim.x + threadIdx.x;
    if (idx >= LSEQ * D) return;
    int l = idx / D;
    int d = idx % D;
    int k = d >> 1;
    const float coef = -9.210340371976184f / (float)D;   // -ln(10000)/300
    float divv = expf((float)(2 * k) * coef);
    float ang  = (float)l * divv;
    g_pe[idx] = (d & 1) ? cosf(ang) : sinf(ang);
}

// ---------------------------------------------------------------------------
// Kernel C: term1. One block per (i, l-chunk of 128). grid (4,300).
// Computes pe[l][i] INLINE (no dependence on pe_kernel output).
// Epilogue: wait(pe done) -> launch_dependents -> atomicAdd into G_DIAG.
// ---------------------------------------------------------------------------
__global__ __launch_bounds__(320) void term1_kernel(
    const int*   __restrict__ x1,
    const int*   __restrict__ x2,
    const float* __restrict__ emb1,
    const float* __restrict__ emb2)
{
    const int chunk = blockIdx.x;          // 0..3
    const int i     = blockIdx.y;          // 0..299
    const int tid   = threadIdx.x;
    const float scale = 17.320508075688775f;  // sqrt(300)
    const float coef  = -9.210340371976184f / (float)D;

    __shared__ float s_sh[CHUNK];
    __shared__ int   r1_sh[CHUNK];

    if (tid < CHUNK) {
        int l  = chunk * CHUNK + tid;
        int t2 = x2[i * LSEQ + l];
        // inline pe[l][i]
        float divv = expf((float)(2 * (i >> 1)) * coef);
        float ang  = (float)l * divv;
        float pev  = (i & 1) ? cosf(ang) : sinf(ang);
        float sv = fmaf(emb2[t2 * D + i], scale, pev);
        s_sh[tid] = sv;
        g_s[i * LSEQ + l] = sv;
        r1_sh[tid] = x1[i * LSEQ + l] * D;
    }
    __syncthreads();

    float r = 0.f;
    if (tid < D) {
        const int e = tid;
        float acc[8];
        #pragma unroll
        for (int u = 0; u < 8; ++u) acc[u] = 0.f;
        #pragma unroll 2
        for (int l = 0; l < CHUNK; l += 8) {
            #pragma unroll
            for (int u = 0; u < 8; ++u)
                acc[u] = fmaf(s_sh[l + u], emb1[r1_sh[l + u] + e], acc[u]);
        }
        r = ((acc[0] + acc[1]) + (acc[2] + acc[3]))
          + ((acc[4] + acc[5]) + (acc[6] + acc[7]));
    }

    GDC_WAIT();      // ensure pe_kernel done before dependents may launch
    GDC_LAUNCH();

    if (tid < D)
        atomicAdd(&G_DIAG[tid * D + i], scale * r);
}

// ---------------------------------------------------------------------------
// Kernel D: term2 GEMM, atomically accumulated into G_DIAG.
//   G_DIAG[e][i] += sum_{l in 128-window kz} s[i,l]*pe[l][e]
// grid (10,10,4), 128 threads (16,8). Thread tile 4e x 2i.
// pe tile staged PRE-WAIT (pe_kernel complete before term1 dependents fire).
// ---------------------------------------------------------------------------
__global__ __launch_bounds__(128) void combine_kernel()
{
    __shared__ float sh_st[128][34];   // [k][i_local]
    __shared__ float sh_pe[128][36];   // [k][e_local], 16B-aligned rows

    const int tx  = threadIdx.x;       // 0..15 -> i = i0 + 2*tx + {0,1}
    const int ty  = threadIdx.y;       // 0..7  -> e = e0 + 4*ty + {0..3}
    const int lin = ty * 16 + tx;
    const int e0  = blockIdx.x * 32;
    const int i0  = blockIdx.y * 32;
    const int kb  = blockIdx.z * 128;

    // PRE-WAIT: stage pe tile (depends only on pe_kernel, already complete)
    #pragma unroll
    for (int t = 0; t < 8; ++t) {
        int idx = lin + t * 128;           // 0..1023
        int row = idx >> 3;                // 0..127 (k_local)
        int cc  = (idx & 7) * 4;           // 0..28
        int e   = e0 + cc;
        float4 v = make_float4(0.f, 0.f, 0.f, 0.f);
        if (e <= D - 4)
            v = *reinterpret_cast<const float4*>(g_pe + (kb + row) * D + e);
        *reinterpret_cast<float4*>(&sh_pe[row][cc]) = v;
    }

    GDC_WAIT();      // term1 complete: g_s valid
    GDC_LAUNCH();    // let fc1 start staging w1

    // stage s tile transposed: 32 i-rows x 128 k
    #pragma unroll
    for (int t = 0; t < 8; ++t) {
        int idx = lin + t * 128;           // 0..1023
        int row = idx >> 5;                // 0..31 (i_local)
        int kk  = (idx & 31) * 4;          // 0..124
        float4 v = make_float4(0.f, 0.f, 0.f, 0.f);
        int ii = i0 + row;
        if (ii < D)
            v = *reinterpret_cast<const float4*>(g_s + ii * LSEQ + kb + kk);
        sh_st[kk][row] = v.x; sh_st[kk + 1][row] = v.y;
        sh_st[kk + 2][row] = v.z; sh_st[kk + 3][row] = v.w;
    }
    __syncthreads();

    float acc0[4] = {0.f, 0.f, 0.f, 0.f};   // i = ip
    float acc1[4] = {0.f, 0.f, 0.f, 0.f};   // i = ip+1
    #pragma unroll 4
    for (int k = 0; k < 128; ++k) {
        float2 sv = *reinterpret_cast<const float2*>(&sh_st[k][2 * tx]);
        float4 pv = *reinterpret_cast<const float4*>(&sh_pe[k][4 * ty]);
        acc0[0] = fmaf(sv.x, pv.x, acc0[0]);
        acc0[1] = fmaf(sv.x, pv.y, acc0[1]);
        acc0[2] = fmaf(sv.x, pv.z, acc0[2]);
        acc0[3] = fmaf(sv.x, pv.w, acc0[3]);
        acc1[0] = fmaf(sv.y, pv.x, acc1[0]);
        acc1[1] = fmaf(sv.y, pv.y, acc1[1]);
        acc1[2] = fmaf(sv.y, pv.z, acc1[2]);
        acc1[3] = fmaf(sv.y, pv.w, acc1[3]);
    }

    const int ip = i0 + 2 * tx;            // even pair (ip, ip+1)
    const int e  = e0 + 4 * ty;
    if (ip < D) {
        #pragma unroll
        for (int u = 0; u < 4; ++u) {
            if (e + u < D) {
                atomicAdd(&G_DIAG[(e + u) * D + ip], acc0[u]);
                atomicAdd(&G_DIAG[(e + u) * D + ip + 1], acc1[u]);
            }
        }
    }
}

// ---------------------------------------------------------------------------
// Kernel E: FC1, atomically accumulated into G_HACC.
//   G_HACC[e][j] += sum_{k in 60-window} diag[e][k] * w1[j][k]
// w1 tile staged PRE-WAIT (independent input). k-major smem tiles.
// Thread tile 4e x 2j: 1 LDS.128 + 1 LDS.64 + 8 FMA per k.
// ---------------------------------------------------------------------------
__global__ __launch_bounds__(128) void fc1_kernel(
    const float* __restrict__ w1)
{
    __shared__ float sat[KT1][36];      // [k][e_local]
    __shared__ float sbt[KT1][36];      // [k][j_local]

    const int tx  = threadIdx.x;        // 0..15 -> j = j0 + 2*tx + {0,1}
    const int ty  = threadIdx.y;        // 0..7  -> e = e0 + 4*ty + {0..3}
    const int lin = ty * 16 + tx;
    const int j0  = blockIdx.x * 32;
    const int e0  = blockIdx.y * 32;
    const int kb  = blockIdx.z * KT1;

    // PRE-WAIT: stage w1 tile (independent of predecessors)
    for (int idx = lin; idx < 32 * 15; idx += 128) {
        int row = idx / 15;
        int kk  = (idx % 15) * 4;
        int k   = kb + kk;                  // max 240+56+3 = 299 < 300
        float4 vb = make_float4(0.f, 0.f, 0.f, 0.f);
        if (j0 + row < D)
            vb = *reinterpret_cast<const float4*>(w1 + (j0 + row) * D + k);
        sbt[kk][row] = vb.x; sbt[kk + 1][row] = vb.y;
        sbt[kk + 2][row] = vb.z; sbt[kk + 3][row] = vb.w;
    }

    GDC_WAIT();      // combine complete: G_DIAG final
    GDC_LAUNCH();    // let fc2 preload w2/b1

    for (int idx = lin; idx < 32 * 15; idx += 128) {
        int row = idx / 15;
        int kk  = (idx % 15) * 4;
        int k   = kb + kk;
        float4 va = make_float4(0.f, 0.f, 0.f, 0.f);
        if (e0 + row < D)
            va = *reinterpret_cast<const float4*>(G_DIAG + (e0 + row) * D + k);
        sat[kk][row] = va.x; sat[kk + 1][row] = va.y;
        sat[kk + 2][row] = va.z; sat[kk + 3][row] = va.w;
    }
    __syncthreads();

    float acc0[4] = {0.f, 0.f, 0.f, 0.f};
    float acc1[4] = {0.f, 0.f, 0.f, 0.f};
    #pragma unroll 6
    for (int k = 0; k < KT1; ++k) {
        float4 a = *reinterpret_cast<const float4*>(&sat[k][4 * ty]);
        float2 b = *reinterpret_cast<const float2*>(&sbt[k][2 * tx]);
        acc0[0] = fmaf(b.x, a.x, acc0[0]);
        acc0[1] = fmaf(b.x, a.y, acc0[1]);
        acc0[2] = fmaf(b.x, a.z, acc0[2]);
        acc0[3] = fmaf(b.x, a.w, acc0[3]);
        acc1[0] = fmaf(b.y, a.x, acc1[0]);
        acc1[1] = fmaf(b.y, a.y, acc1[1]);
        acc1[2] = fmaf(b.y, a.z, acc1[2]);
        acc1[3] = fmaf(b.y, a.w, acc1[3]);
    }

    const int jp = j0 + 2 * tx;             // even pair
    const int e  = e0 + 4 * ty;
    if (jp < D) {
        #pragma unroll
        for (int u = 0; u < 4; ++u) {
            if (e + u < D) {
                atomicAdd(&G_HACC[(e + u) * D + jp], acc0[u]);
                atomicAdd(&G_HACC[(e + u) * D + jp + 1], acc1[u]);
            }
        }
    }
}

// ---------------------------------------------------------------------------
// Kernel F: FC2 + softmax. One block per e-row. w2/b1 preloaded PRE-WAIT.
// ---------------------------------------------------------------------------
__global__ __launch_bounds__(128) void fc2_kernel(
    const float* __restrict__ b1,
    const float* __restrict__ w2,
    const float* __restrict__ b2,
    float*       __restrict__ out)
{
    const int e   = blockIdx.x;
    const int tid = threadIdx.x;

    // PRE-WAIT: preload weights/bias for this thread's j's
    float wv[3][OUTC];
    float bv[3];
    #pragma unroll
    for (int t = 0; t < 3; ++t) {
        int j = tid + t * 128;
        if (j < D) {
            bv[t] = b1[j];
            #pragma unroll
            for (int o = 0; o < OUTC; ++o) wv[t][o] = w2[o * D + j];
        } else {
            bv[t] = 0.f;
            #pragma unroll
            for (int o = 0; o < OUTC; ++o) wv[t][o] = 0.f;
        }
    }

    GDC_WAIT();      // fc1 complete: G_HACC final

    float p[OUTC] = {0.f, 0.f, 0.f, 0.f};
    #pragma unroll
    for (int t = 0; t < 3; ++t) {
        int j = tid + t * 128;
        if (j < D) {
            float hv = fmaxf(G_HACC[e * D + j] + bv[t], 0.f);
            #pragma unroll
            for (int o = 0; o < OUTC; ++o)
                p[o] = fmaf(hv, wv[t][o], p[o]);
        }
    }

    #pragma unroll
    for (int off = 16; off > 0; off >>= 1) {
        #pragma unroll
        for (int o = 0; o < OUTC; ++o)
            p[o] += __shfl_xor_sync(0xFFFFFFFFu, p[o], off);
    }

    __shared__ float red[4][OUTC];
    const int wid = tid >> 5, lid = tid & 31;
    if (lid == 0) {
        #pragma unroll
        for (int o = 0; o < OUTC; ++o) red[wid][o] = p[o];
    }
    __syncthreads();

    if (tid == 0) {
        float logits[OUTC];
        #pragma unroll
        for (int o = 0; o < OUTC; ++o)
            logits[o] = red[0][o] + red[1][o] + red[2][o] + red[3][o] + b2[o];
        float m = fmaxf(fmaxf(logits[0], logits[1]), fmaxf(logits[2], logits[3]));
        float es[OUTC], ssum = 0.f;
        #pragma unroll
        for (int o = 0; o < OUTC; ++o) { es[o] = expf(logits[o] - m); ssum += es[o]; }
        float inv = 1.f / ssum;
        #pragma unroll
        for (int o = 0; o < OUTC; ++o) out[e * OUTC + o] = es[o] * inv;
    }
}

// ---------------------------------------------------------------------------
// Launch with programmatic stream serialization on the dependent chain.
// Inputs: x1, x2 (i32 [512*512]); emb1, emb2 (f32 [32000*300]);
// w1 (f32 [300*300]); b1 (f32 [300]); w2 (f32 [4*300]); b2 (f32 [4]).
// Output: f32 [300*4].
// ---------------------------------------------------------------------------
extern "C" void kernel_launch(void* const* d_in, const int* in_sizes, int n_in,
                              void* d_out, int out_size) {
    const int*   x1   = (const int*)  d_in[0];
    const int*   x2   = (const int*)  d_in[1];
    const float* emb1 = (const float*)d_in[2];
    const float* emb2 = (const float*)d_in[3];
    const float* w1   = (const float*)d_in[4];
    const float* b1   = (const float*)d_in[5];
    const float* w2   = (const float*)d_in[6];
    const float* b2   = (const float*)d_in[7];
    float* out = (float*)d_out;

    cudaLaunchAttribute pss[1];
    pss[0].id = cudaLaunchAttributeProgrammaticStreamSerialization;
    pss[0].val.programmaticStreamSerializationAllowed = 1;

    // A: zero (normal)
    zero_kernel<<<(2 * D * D / 4 + 255) / 256, 256>>>();
    // B: pe (normal; fires launch_dependents at entry)
    pe_kernel<<<(LSEQ * D + 255) / 256, 256>>>();

    // C: term1 (PSS — launches as soon as pe enters)
    {
        cudaLaunchConfig_t cfg = {};
        cfg.gridDim = dim3(NCH, D); cfg.blockDim = dim3(320);
        cfg.attrs = pss; cfg.numAttrs = 1;
        cudaLaunchKernelEx(&cfg, term1_kernel, x1, x2, emb1, emb2);
    }
    // D: combine (PSS)
    {
        cudaLaunchConfig_t cfg = {};
        cfg.gridDim = dim3(10, 10, DKZ); cfg.blockDim = dim3(16, 8);
        cfg.attrs = pss; cfg.numAttrs = 1;
        cudaLaunchKernelEx(&cfg, combine_kernel);
    }
    // E: fc1 (PSS)
    {
        cudaLaunchConfig_t cfg = {};
        cfg.gridDim = dim3(10, 10, HKZ); cfg.blockDim = dim3(16, 8);
        cfg.attrs = pss; cfg.numAttrs = 1;
        cudaLaunchKernelEx(&cfg, fc1_kernel, w1);
    }
    // F: fc2 (PSS)
    {
        cudaLaunchConfig_t cfg = {};
        cfg.gridDim = dim3(D); cfg.blockDim = dim3(128);
        cfg.attrs = pss; cfg.numAttrs = 1;
        cudaLaunchKernelEx(&cfg, fc2_kernel, b1, w2, b2, out);
    }
}